// round 11
// baseline (speedup 1.0000x reference)
#include <cuda_runtime.h>
#include <cuda_fp16.h>
#include <cstdint>

#define N_NODES 100000
#define N_FEAT  128
#define N_EDGES 1600000
#define SCAN_CHUNK 1024
#define NBLK ((N_NODES + SCAN_CHUNK - 1) / SCAN_CHUNK)   // 98

// Scratch (__device__ globals: allocation-free).
__device__ int    g_degi[N_NODES];
__device__ int    g_rowstart[N_NODES];
__device__ int    g_cursor[N_NODES];
__device__ int    g_bsum[128];
__device__ int    g_srcs[N_EDGES];
__device__ float  g_dinv[N_NODES];
__device__ float  g_Bfrag[16 * 16 * 32 * 2];         // W hi fragments {hi0,hi1}
__device__ __half g_xwh[(size_t)N_NODES * N_FEAT];   // x@W^T (UNscaled), fp16

__device__ __forceinline__ uint32_t tf32_rna(float v) {
    uint32_t r;
    asm("cvt.rna.tf32.f32 %0, %1;" : "=r"(r) : "f"(v));
    return r;
}

// ---------------------------------------------------------------------------
// Branch A1: pack W hi-fragments (x/W path only)
__global__ void k_bpack(const float* __restrict__ W) {
    const int t = blockIdx.x * blockDim.x + threadIdx.x;
    if (t < 16 * 16 * 32) {
        const int lane = t & 31;
        const int nc   = (t >> 5) & 15;
        const int kc   = t >> 9;
        const int k = kc * 8 + (lane & 3);
        const int n = nc * 8 + (lane >> 2);
        const uint32_t h0 = tf32_rna(W[n * N_FEAT + k]);      // W^T[k][n]
        const uint32_t h1 = tf32_rna(W[n * N_FEAT + k + 4]);
        reinterpret_cast<float2*>(g_Bfrag)[t] =
            make_float2(__uint_as_float(h0), __uint_as_float(h1));
    }
}

// Branch B1: zero degree counters
__global__ void k_deg_init() {
    const int i = blockIdx.x * blockDim.x + threadIdx.x;
    if (i < N_NODES) g_degi[i] = 0;
}

// Branch B2: degree count
__global__ void k_deg_count(const int* __restrict__ col) {
    int e = blockIdx.x * blockDim.x + threadIdx.x;
    if (e < N_EDGES) atomicAdd(&g_degi[col[e]], 1);
}

// Branch B3: scan stage 1 (+ dinv)
__global__ void k_scan1() {
    __shared__ int sh[256];
    const int t = threadIdx.x;
    const int base = blockIdx.x * SCAN_CHUNK + t * 4;
    int v[4], s = 0;
    #pragma unroll
    for (int i = 0; i < 4; ++i) {
        int idx = base + i;
        v[i] = (idx < N_NODES) ? g_degi[idx] : 0;
        if (idx < N_NODES) g_dinv[idx] = rsqrtf((float)(v[i] + 1));
        s += v[i];
    }
    sh[t] = s; __syncthreads();
    #pragma unroll
    for (int off = 1; off < 256; off <<= 1) {
        int add = (t >= off) ? sh[t - off] : 0;
        __syncthreads();
        sh[t] += add;
        __syncthreads();
    }
    if (t == 255) g_bsum[blockIdx.x] = sh[255];
    int run = sh[t] - s;
    #pragma unroll
    for (int i = 0; i < 4; ++i) {
        int idx = base + i;
        if (idx < N_NODES) g_rowstart[idx] = run;
        run += v[i];
    }
}

// Branch B4: fused scan stages 2+3
__global__ void k_scan23() {
    __shared__ int sh[128];
    const int t = threadIdx.x;
    int v = 0;
    if (t < 128) { v = (t < NBLK) ? g_bsum[t] : 0; sh[t] = v; }
    __syncthreads();
    #pragma unroll
    for (int off = 1; off < 128; off <<= 1) {
        int add = 0;
        if (t < 128 && t >= off) add = sh[t - off];
        __syncthreads();
        if (t < 128) sh[t] += add;
        __syncthreads();
    }
    if (t < 128) sh[t] -= v;
    __syncthreads();
    const int i = blockIdx.x * blockDim.x + t;
    if (i < N_NODES) {
        int rs = g_rowstart[i] + sh[i >> 10];
        g_rowstart[i] = rs;
        g_cursor[i]   = rs;
    }
}

// Branch B5: bucket-fill
__global__ void k_fill(const int* __restrict__ ei) {
    int e = blockIdx.x * blockDim.x + threadIdx.x;
    if (e < N_EDGES) {
        int c = ei[N_EDGES + e];
        int pos = atomicAdd(&g_cursor[c], 1);
        g_srcs[pos] = ei[e];
    }
}

// ---------------------------------------------------------------------------
#define MMA_TF32(acc, a0, a1, a2, a3, b0, b1)                                  \
    asm volatile("mma.sync.aligned.m16n8k8.row.col.f32.tf32.tf32.f32 "         \
                 "{%0,%1,%2,%3}, {%4,%5,%6,%7}, {%8,%9}, {%0,%1,%2,%3};"       \
                 : "+f"(acc[0]), "+f"(acc[1]), "+f"(acc[2]), "+f"(acc[3])      \
                 : "r"(a0), "r"(a1), "r"(a2), "r"(a3), "r"(b0), "r"(b1))

// Branch A2 (profiled): g_xwh = half(x @ W^T)  -- NO dinv (moved to gather).
// R7 mainloop verbatim: 2-term tf32 split, 8 warps, warp tile 16x64.
__global__ __launch_bounds__(256) void k_gemm(const float* __restrict__ x) {
    __shared__ float xs[64][132];
    const int t    = threadIdx.x;
    const int warp = t >> 5;
    const int lane = t & 31;
    const int row0  = blockIdx.x * 64;
    const int nrows = min(64, N_NODES - row0);

    const float4* src = reinterpret_cast<const float4*>(x + (size_t)row0 * N_FEAT);
    for (int idx = t; idx < nrows * 32; idx += 256) {
        const int r = idx >> 5, c4 = idx & 31;
        *reinterpret_cast<float4*>(&xs[r][c4 * 4]) = src[idx];
    }
    __syncthreads();

    const int g   = lane >> 2;
    const int tg  = lane & 3;
    const int rb  = (warp & 3) * 16;
    const int nc0 = (warp >> 2) * 8;

    float acc[8][4];
    #pragma unroll
    for (int j = 0; j < 8; ++j)
        acc[j][0] = acc[j][1] = acc[j][2] = acc[j][3] = 0.f;

    const float2* bptr = reinterpret_cast<const float2*>(g_Bfrag) + nc0 * 32 + lane;

    float2 bcur[8];
    #pragma unroll
    for (int j = 0; j < 8; ++j) bcur[j] = bptr[j * 32];

    #pragma unroll
    for (int kc = 0; kc < 16; ++kc) {
        const int k0 = kc * 8;
        const float ar0 = xs[rb + g][k0 + tg];
        const float ar1 = xs[rb + g + 8][k0 + tg];
        const float ar2 = xs[rb + g][k0 + tg + 4];
        const float ar3 = xs[rb + g + 8][k0 + tg + 4];
        const uint32_t h0 = tf32_rna(ar0), h1 = tf32_rna(ar1);
        const uint32_t h2 = tf32_rna(ar2), h3 = tf32_rna(ar3);
        const uint32_t l0 = __float_as_uint(ar0 - __uint_as_float(h0));
        const uint32_t l1 = __float_as_uint(ar1 - __uint_as_float(h1));
        const uint32_t l2 = __float_as_uint(ar2 - __uint_as_float(h2));
        const uint32_t l3 = __float_as_uint(ar3 - __uint_as_float(h3));

        float2 bnxt[8];
        if (kc < 15) {
            #pragma unroll
            for (int j = 0; j < 8; ++j) bnxt[j] = bptr[(kc + 1) * 512 + j * 32];
        }

        #pragma unroll
        for (int j = 0; j < 8; ++j) {
            const uint32_t bh0 = __float_as_uint(bcur[j].x);
            const uint32_t bh1 = __float_as_uint(bcur[j].y);
            MMA_TF32(acc[j], h0, h1, h2, h3, bh0, bh1);   // hi*hi
            MMA_TF32(acc[j], l0, l1, l2, l3, bh0, bh1);   // lo*hi
        }
        if (kc < 15) {
            #pragma unroll
            for (int j = 0; j < 8; ++j) bcur[j] = bnxt[j];
        }
    }

    const int r0 = row0 + rb + g;
    const int r1 = r0 + 8;
    #pragma unroll
    for (int j = 0; j < 8; ++j) {
        const int col = (nc0 + j) * 8 + tg * 2;
        if (r0 < N_NODES)
            *reinterpret_cast<__half2*>(&g_xwh[(size_t)r0 * N_FEAT + col]) =
                __floats2half2_rn(acc[j][0], acc[j][1]);
        if (r1 < N_NODES)
            *reinterpret_cast<__half2*>(&g_xwh[(size_t)r1 * N_FEAT + col]) =
                __floats2half2_rn(acc[j][2], acc[j][3]);
    }
}

// ---------------------------------------------------------------------------
// Join: pull aggregation. xwh is unscaled; apply dinv[s] per gathered row
// (warp-uniform broadcast load), dinv[c] for self + final scale.
__global__ __launch_bounds__(256) void k_gather(const float* __restrict__ b,
                                                float* __restrict__ out) {
    const int warp = (blockIdx.x * blockDim.x + threadIdx.x) >> 5;
    const int lane = threadIdx.x & 31;
    if (warp >= N_NODES) return;
    const int c = warp;

    const int base = g_rowstart[c];
    const int cnt  = g_degi[c];

    float4 a0 = make_float4(0.f,0.f,0.f,0.f), a1 = a0, a2 = a0, a3 = a0;
    const uint2* xw = reinterpret_cast<const uint2*>(g_xwh);   // 8B = 4 halves

    int i = 0;
    for (; i + 4 <= cnt; i += 4) {
        const int s0 = g_srcs[base + i + 0];
        const int s1 = g_srcs[base + i + 1];
        const int s2 = g_srcs[base + i + 2];
        const int s3 = g_srcs[base + i + 3];
        const float d0 = g_dinv[s0], d1 = g_dinv[s1];
        const float d2 = g_dinv[s2], d3 = g_dinv[s3];
        const uint2 v0 = xw[(size_t)s0 * 32 + lane];
        const uint2 v1 = xw[(size_t)s1 * 32 + lane];
        const uint2 v2 = xw[(size_t)s2 * 32 + lane];
        const uint2 v3 = xw[(size_t)s3 * 32 + lane];
        {
            const float2 p = __half22float2(*(const __half2*)&v0.x);
            const float2 q = __half22float2(*(const __half2*)&v0.y);
            a0.x = fmaf(p.x, d0, a0.x); a0.y = fmaf(p.y, d0, a0.y);
            a0.z = fmaf(q.x, d0, a0.z); a0.w = fmaf(q.y, d0, a0.w);
        }
        {
            const float2 p = __half22float2(*(const __half2*)&v1.x);
            const float2 q = __half22float2(*(const __half2*)&v1.y);
            a1.x = fmaf(p.x, d1, a1.x); a1.y = fmaf(p.y, d1, a1.y);
            a1.z = fmaf(q.x, d1, a1.z); a1.w = fmaf(q.y, d1, a1.w);
        }
        {
            const float2 p = __half22float2(*(const __half2*)&v2.x);
            const float2 q = __half22float2(*(const __half2*)&v2.y);
            a2.x = fmaf(p.x, d2, a2.x); a2.y = fmaf(p.y, d2, a2.y);
            a2.z = fmaf(q.x, d2, a2.z); a2.w = fmaf(q.y, d2, a2.w);
        }
        {
            const float2 p = __half22float2(*(const __half2*)&v3.x);
            const float2 q = __half22float2(*(const __half2*)&v3.y);
            a3.x = fmaf(p.x, d3, a3.x); a3.y = fmaf(p.y, d3, a3.y);
            a3.z = fmaf(q.x, d3, a3.z); a3.w = fmaf(q.y, d3, a3.w);
        }
    }
    for (; i < cnt; ++i) {
        const int s = g_srcs[base + i];
        const float ds = g_dinv[s];
        const uint2 v = xw[(size_t)s * 32 + lane];
        const float2 p = __half22float2(*(const __half2*)&v.x);
        const float2 q = __half22float2(*(const __half2*)&v.y);
        a0.x = fmaf(p.x, ds, a0.x); a0.y = fmaf(p.y, ds, a0.y);
        a0.z = fmaf(q.x, ds, a0.z); a0.w = fmaf(q.y, ds, a0.w);
    }

    const float nc = g_dinv[c];
    const uint2 vs = xw[(size_t)c * 32 + lane];
    const float2 sp = __half22float2(*(const __half2*)&vs.x);
    const float2 sq = __half22float2(*(const __half2*)&vs.y);
    float4 acc = make_float4(a0.x + a1.x + a2.x + a3.x + sp.x * nc,
                             a0.y + a1.y + a2.y + a3.y + sp.y * nc,
                             a0.z + a1.z + a2.z + a3.z + sq.x * nc,
                             a0.w + a1.w + a2.w + a3.w + sq.y * nc);
    const float4 bv = reinterpret_cast<const float4*>(b)[lane];
    reinterpret_cast<float4*>(out + (size_t)c * N_FEAT)[lane] =
        make_float4(acc.x * nc + bv.x, acc.y * nc + bv.y,
                    acc.z * nc + bv.z, acc.w * nc + bv.w);
}

// ---------------------------------------------------------------------------
extern "C" void kernel_launch(void* const* d_in, const int* in_sizes, int n_in,
                              void* d_out, int out_size) {
    const float* x  = (const float*)d_in[0];
    const int*   ei = (const int*)  d_in[1];
    const float* W  = (const float*)d_in[2];
    const float* b  = (const float*)d_in[3];
    float* out = (float*)d_out;

    static cudaStream_t sB = nullptr;
    static cudaEvent_t evFork = nullptr, evJoinB = nullptr;
    if (sB == nullptr) {
        cudaStreamCreateWithFlags(&sB, cudaStreamNonBlocking);
        cudaEventCreateWithFlags(&evFork,  cudaEventDisableTiming);
        cudaEventCreateWithFlags(&evJoinB, cudaEventDisableTiming);
    }

    // Fork: side branch B joins the capture via event dependency.
    cudaEventRecord(evFork, 0);
    cudaStreamWaitEvent(sB, evFork, 0);

    // Branch A (main stream): W pack -> GEMM  (tensor-bound)
    k_bpack<<<(16 * 16 * 32 + 255) / 256, 256>>>(W);
    // Branch B (side stream): CSR build (atomic/memory-bound)
    k_deg_init <<<(N_NODES + 255) / 256, 256, 0, sB>>>();
    k_deg_count<<<(N_EDGES + 255) / 256, 256, 0, sB>>>(ei + N_EDGES);
    k_gemm<<<(N_NODES + 63) / 64, 256>>>(x);            // 4th kernel (profiled)
    k_scan1    <<<NBLK, 256, 0, sB>>>();
    k_scan23   <<<(N_NODES + 255) / 256, 256, 0, sB>>>();
    k_fill     <<<(N_EDGES + 255) / 256, 256, 0, sB>>>(ei);

    // Join: gather needs both branches.
    cudaEventRecord(evJoinB, sB);
    cudaStreamWaitEvent(0, evJoinB, 0);
    k_gather<<<(N_NODES * 32 + 255) / 256, 256>>>(b, out);
}

// round 14
// speedup vs baseline: 1.0195x; 1.0195x over previous
#include <cuda_runtime.h>
#include <cuda_fp16.h>
#include <cstdint>

#define N_NODES 100000
#define N_FEAT  128
#define N_EDGES 1600000
#define SCAN_CHUNK 1024
#define NBLK ((N_NODES + SCAN_CHUNK - 1) / SCAN_CHUNK)   // 98

// Scratch (__device__ globals: allocation-free).
__device__ int      g_degi[N_NODES];
__device__ int      g_rowstart[N_NODES];
__device__ int      g_cursor[N_NODES];
__device__ int      g_bsum[128];
__device__ int      g_srcs[N_EDGES];
__device__ float    g_dinv[N_NODES];
__device__ uint32_t g_BfragH[8 * 16 * 32 * 2];       // fp16 W frags (half2 each)
__device__ __half   g_xwh[(size_t)N_NODES * N_FEAT]; // (x@W^T)*dinv[row], fp16

// ---------------------------------------------------------------------------
// 1) fused: zero degree counters + pack W into fp16 m16n8k16 B-fragments.
//    For (kc 0..7, nc 0..15, lane): k = kc*16 + 2*tg, n = nc*8 + g:
//      b0 = {W[n][k],   W[n][k+1]}   (k-half [0,8))
//      b1 = {W[n][k+8], W[n][k+9]}   (k-half [8,16))
//    Stored so warp-half h = nc>>3 reads 16 uints/lane contiguous per kc:
//      uidx = ((kc*2 + h)*32 + lane)*16 + (nc&7)*2 + reg
__global__ void k_init_bpack(const float* __restrict__ W) {
    const int t = blockIdx.x * blockDim.x + threadIdx.x;
    if (t < N_NODES) g_degi[t] = 0;
    if (t < 8 * 16 * 32) {
        const int lane = t & 31;
        const int nc   = (t >> 5) & 15;
        const int kc   = t >> 9;
        const int g  = lane >> 2;
        const int tg = lane & 3;
        const int k = kc * 16 + tg * 2;
        const int n = nc * 8 + g;
        const __half2 b0 = __floats2half2_rn(W[n * N_FEAT + k],     W[n * N_FEAT + k + 1]);
        const __half2 b1 = __floats2half2_rn(W[n * N_FEAT + k + 8], W[n * N_FEAT + k + 9]);
        const int base = ((kc * 2 + (nc >> 3)) * 32 + lane) * 16 + (nc & 7) * 2;
        g_BfragH[base + 0] = *reinterpret_cast<const uint32_t*>(&b0);
        g_BfragH[base + 1] = *reinterpret_cast<const uint32_t*>(&b1);
    }
}

// 2) degree count
__global__ void k_deg_count(const int* __restrict__ col) {
    int e = blockIdx.x * blockDim.x + threadIdx.x;
    if (e < N_EDGES) atomicAdd(&g_degi[col[e]], 1);
}

// 3) scan stage 1 (+ dinv)
__global__ void k_scan1() {
    __shared__ int sh[256];
    const int t = threadIdx.x;
    const int base = blockIdx.x * SCAN_CHUNK + t * 4;
    int v[4], s = 0;
    #pragma unroll
    for (int i = 0; i < 4; ++i) {
        int idx = base + i;
        v[i] = (idx < N_NODES) ? g_degi[idx] : 0;
        if (idx < N_NODES) g_dinv[idx] = rsqrtf((float)(v[i] + 1));
        s += v[i];
    }
    sh[t] = s; __syncthreads();
    #pragma unroll
    for (int off = 1; off < 256; off <<= 1) {
        int add = (t >= off) ? sh[t - off] : 0;
        __syncthreads();
        sh[t] += add;
        __syncthreads();
    }
    if (t == 255) g_bsum[blockIdx.x] = sh[255];
    int run = sh[t] - s;
    #pragma unroll
    for (int i = 0; i < 4; ++i) {
        int idx = base + i;
        if (idx < N_NODES) g_rowstart[idx] = run;
        run += v[i];
    }
}

// ---------------------------------------------------------------------------
#define MMA_F16(acc, a0, a1, a2, a3, b0, b1)                                   \
    asm volatile("mma.sync.aligned.m16n8k16.row.col.f32.f16.f16.f32 "          \
                 "{%0,%1,%2,%3}, {%4,%5,%6,%7}, {%8,%9}, {%0,%1,%2,%3};"       \
                 : "+f"(acc[0]), "+f"(acc[1]), "+f"(acc[2]), "+f"(acc[3])      \
                 : "r"(a0), "r"(a1), "r"(a2), "r"(a3), "r"(b0), "r"(b1))

// 4) GEMM (profiled): g_xwh = half((x @ W^T) * dinv[row]).
//    fp16 2-term split: acc += Ahi*Bhi + Alo*Bhi (fp32 accum).
//    Block 256 / 8 warps, tile 64x128, warp tile 16x64, 8 kc-steps of K=16.
__global__ __launch_bounds__(256) void k_gemm(const float* __restrict__ x) {
    __shared__ float xs[64][132];
    const int t    = threadIdx.x;
    const int warp = t >> 5;
    const int lane = t & 31;
    const int row0  = blockIdx.x * 64;
    const int nrows = min(64, N_NODES - row0);

    const float4* src = reinterpret_cast<const float4*>(x + (size_t)row0 * N_FEAT);
    for (int idx = t; idx < nrows * 32; idx += 256) {
        const int r = idx >> 5, c4 = idx & 31;
        *reinterpret_cast<float4*>(&xs[r][c4 * 4]) = src[idx];
    }
    __syncthreads();

    const int g   = lane >> 2;
    const int tg  = lane & 3;
    const int rb  = (warp & 3) * 16;
    const int h   = warp >> 2;        // N-half: nc0 = h*8
    const int nc0 = h * 8;

    float acc[8][4];
    #pragma unroll
    for (int j = 0; j < 8; ++j)
        acc[j][0] = acc[j][1] = acc[j][2] = acc[j][3] = 0.f;

    // B: per kc, 4 uint4 at ((kc*2 + h)*32 + lane)*4  (uint4 units)
    const uint4* bp = reinterpret_cast<const uint4*>(g_BfragH)
                      + ((size_t)h * 32 + lane) * 4;

    uint4 bcur[4];
    #pragma unroll
    for (int j = 0; j < 4; ++j) bcur[j] = bp[j];

    #pragma unroll
    for (int kc = 0; kc < 8; ++kc) {
        const int k16 = kc * 16;
        // A: 4 float2 loads (rows g, g+8; k-halves 0/8)
        const float2 f00 = *reinterpret_cast<const float2*>(&xs[rb + g][k16 + tg * 2]);
        const float2 f10 = *reinterpret_cast<const float2*>(&xs[rb + g + 8][k16 + tg * 2]);
        const float2 f01 = *reinterpret_cast<const float2*>(&xs[rb + g][k16 + tg * 2 + 8]);
        const float2 f11 = *reinterpret_cast<const float2*>(&xs[rb + g + 8][k16 + tg * 2 + 8]);
        // hi = fp16(x), lo = fp16(x - float(hi))
        const __half2 h00 = __floats2half2_rn(f00.x, f00.y);
        const __half2 h10 = __floats2half2_rn(f10.x, f10.y);
        const __half2 h01 = __floats2half2_rn(f01.x, f01.y);
        const __half2 h11 = __floats2half2_rn(f11.x, f11.y);
        const float2 e00 = __half22float2(h00), e10 = __half22float2(h10);
        const float2 e01 = __half22float2(h01), e11 = __half22float2(h11);
        const __half2 q00 = __floats2half2_rn(f00.x - e00.x, f00.y - e00.y);
        const __half2 q10 = __floats2half2_rn(f10.x - e10.x, f10.y - e10.y);
        const __half2 q01 = __floats2half2_rn(f01.x - e01.x, f01.y - e01.y);
        const __half2 q11 = __floats2half2_rn(f11.x - e11.x, f11.y - e11.y);
        const uint32_t ah0 = *reinterpret_cast<const uint32_t*>(&h00);
        const uint32_t ah1 = *reinterpret_cast<const uint32_t*>(&h10);
        const uint32_t ah2 = *reinterpret_cast<const uint32_t*>(&h01);
        const uint32_t ah3 = *reinterpret_cast<const uint32_t*>(&h11);
        const uint32_t al0 = *reinterpret_cast<const uint32_t*>(&q00);
        const uint32_t al1 = *reinterpret_cast<const uint32_t*>(&q10);
        const uint32_t al2 = *reinterpret_cast<const uint32_t*>(&q01);
        const uint32_t al3 = *reinterpret_cast<const uint32_t*>(&q11);

        uint4 bnxt[4];
        if (kc < 7) {
            #pragma unroll
            for (int j = 0; j < 4; ++j) bnxt[j] = bp[(kc + 1) * 256 + j];
        }

        // bcur = 16 uints: (nc&7)*2 + reg; j-th nc uses uints {2j, 2j+1}
        #pragma unroll
        for (int j = 0; j < 4; ++j) {
            const uint32_t b00 = bcur[j].x, b01 = bcur[j].y;   // nc = 2j
            const uint32_t b10 = bcur[j].z, b11 = bcur[j].w;   // nc = 2j+1
            MMA_F16(acc[2*j],     ah0, ah1, ah2, ah3, b00, b01);
            MMA_F16(acc[2*j],     al0, al1, al2, al3, b00, b01);
            MMA_F16(acc[2*j + 1], ah0, ah1, ah2, ah3, b10, b11);
            MMA_F16(acc[2*j + 1], al0, al1, al2, al3, b10, b11);
        }
        if (kc < 7) {
            #pragma unroll
            for (int j = 0; j < 4; ++j) bcur[j] = bnxt[j];
        }
    }

    // Epilogue: c0/c1 -> (row0+rb+g, col/col+1); c2/c3 -> (+8 rows).
    const int r0 = row0 + rb + g;
    const int r1 = r0 + 8;
    const float d0 = (r0 < N_NODES) ? g_dinv[r0] : 0.f;
    const float d1 = (r1 < N_NODES) ? g_dinv[r1] : 0.f;
    #pragma unroll
    for (int j = 0; j < 8; ++j) {
        const int col = (nc0 + j) * 8 + tg * 2;
        if (r0 < N_NODES)
            *reinterpret_cast<__half2*>(&g_xwh[(size_t)r0 * N_FEAT + col]) =
                __floats2half2_rn(acc[j][0] * d0, acc[j][1] * d0);
        if (r1 < N_NODES)
            *reinterpret_cast<__half2*>(&g_xwh[(size_t)r1 * N_FEAT + col]) =
                __floats2half2_rn(acc[j][2] * d1, acc[j][3] * d1);
    }
}

// 5) fused scan stages 2+3
__global__ void k_scan23() {
    __shared__ int sh[128];
    const int t = threadIdx.x;
    int v = 0;
    if (t < 128) { v = (t < NBLK) ? g_bsum[t] : 0; sh[t] = v; }
    __syncthreads();
    #pragma unroll
    for (int off = 1; off < 128; off <<= 1) {
        int add = 0;
        if (t < 128 && t >= off) add = sh[t - off];
        __syncthreads();
        if (t < 128) sh[t] += add;
        __syncthreads();
    }
    if (t < 128) sh[t] -= v;
    __syncthreads();
    const int i = blockIdx.x * blockDim.x + t;
    if (i < N_NODES) {
        int rs = g_rowstart[i] + sh[i >> 10];
        g_rowstart[i] = rs;
        g_cursor[i]   = rs;
    }
}

// 6) bucket-fill
__global__ void k_fill(const int* __restrict__ ei) {
    int e = blockIdx.x * blockDim.x + threadIdx.x;
    if (e < N_EDGES) {
        int c = ei[N_EDGES + e];
        int pos = atomicAdd(&g_cursor[c], 1);
        g_srcs[pos] = ei[e];
    }
}

// ---------------------------------------------------------------------------
// 7) Pull aggregation (R10 version): one warp per target; fp16 rows, fp32 acc.
__global__ __launch_bounds__(256) void k_gather(const float* __restrict__ b,
                                                float* __restrict__ out) {
    const int warp = (blockIdx.x * blockDim.x + threadIdx.x) >> 5;
    const int lane = threadIdx.x & 31;
    if (warp >= N_NODES) return;
    const int c = warp;

    const int base = g_rowstart[c];
    const int cnt  = g_degi[c];

    float4 a0 = make_float4(0.f,0.f,0.f,0.f), a1 = a0, a2 = a0, a3 = a0;
    const uint2* xw = reinterpret_cast<const uint2*>(g_xwh);   // 8B = 4 halves

    int i = 0;
    for (; i + 4 <= cnt; i += 4) {
        const int s0 = g_srcs[base + i + 0];
        const int s1 = g_srcs[base + i + 1];
        const int s2 = g_srcs[base + i + 2];
        const int s3 = g_srcs[base + i + 3];
        const uint2 v0 = xw[(size_t)s0 * 32 + lane];
        const uint2 v1 = xw[(size_t)s1 * 32 + lane];
        const uint2 v2 = xw[(size_t)s2 * 32 + lane];
        const uint2 v3 = xw[(size_t)s3 * 32 + lane];
        {
            const float2 p = __half22float2(*(const __half2*)&v0.x);
            const float2 q = __half22float2(*(const __half2*)&v0.y);
            a0.x += p.x; a0.y += p.y; a0.z += q.x; a0.w += q.y;
        }
        {
            const float2 p = __half22float2(*(const __half2*)&v1.x);
            const float2 q = __half22float2(*(const __half2*)&v1.y);
            a1.x += p.x; a1.y += p.y; a1.z += q.x; a1.w += q.y;
        }
        {
            const float2 p = __half22float2(*(const __half2*)&v2.x);
            const float2 q = __half22float2(*(const __half2*)&v2.y);
            a2.x += p.x; a2.y += p.y; a2.z += q.x; a2.w += q.y;
        }
        {
            const float2 p = __half22float2(*(const __half2*)&v3.x);
            const float2 q = __half22float2(*(const __half2*)&v3.y);
            a3.x += p.x; a3.y += p.y; a3.z += q.x; a3.w += q.y;
        }
    }
    for (; i < cnt; ++i) {
        const int s = g_srcs[base + i];
        const uint2 v = xw[(size_t)s * 32 + lane];
        const float2 p = __half22float2(*(const __half2*)&v.x);
        const float2 q = __half22float2(*(const __half2*)&v.y);
        a0.x += p.x; a0.y += p.y; a0.z += q.x; a0.w += q.y;
    }

    const uint2 vs = xw[(size_t)c * 32 + lane];
    const float2 sp = __half22float2(*(const __half2*)&vs.x);
    const float2 sq = __half22float2(*(const __half2*)&vs.y);
    float4 acc = make_float4(a0.x + a1.x + a2.x + a3.x + sp.x,
                             a0.y + a1.y + a2.y + a3.y + sp.y,
                             a0.z + a1.z + a2.z + a3.z + sq.x,
                             a0.w + a1.w + a2.w + a3.w + sq.y);
    const float nc = g_dinv[c];
    const float4 bv = reinterpret_cast<const float4*>(b)[lane];
    reinterpret_cast<float4*>(out + (size_t)c * N_FEAT)[lane] =
        make_float4(acc.x * nc + bv.x, acc.y * nc + bv.y,
                    acc.z * nc + bv.z, acc.w * nc + bv.w);
}

// ---------------------------------------------------------------------------
extern "C" void kernel_launch(void* const* d_in, const int* in_sizes, int n_in,
                              void* d_out, int out_size) {
    const float* x  = (const float*)d_in[0];
    const int*   ei = (const int*)  d_in[1];
    const float* W  = (const float*)d_in[2];
    const float* b  = (const float*)d_in[3];
    float* out = (float*)d_out;

    k_init_bpack<<<(N_NODES + 255) / 256, 256>>>(W);               // 1
    k_deg_count <<<(N_EDGES + 255) / 256, 256>>>(ei + N_EDGES);    // 2
    k_scan1     <<<NBLK, 256>>>();                                 // 3 (dinv ready)
    k_gemm      <<<(N_NODES + 63) / 64, 256>>>(x);                 // 4 (profiled)
    k_scan23    <<<(N_NODES + 255) / 256, 256>>>();                // 5
    k_fill      <<<(N_EDGES + 255) / 256, 256>>>(ei);              // 6
    k_gather    <<<(N_NODES * 32 + 255) / 256, 256>>>(b, out);     // 7
}